// round 1
// baseline (speedup 1.0000x reference)
#include <cuda_runtime.h>

#define B 4
#define N 8192
#define C 128
#define S 2048
#define K 32
#define D 256      // 2C
#define CP 132     // C+3 padded to 132 (mult of 4)
#define R2 0.01f
#define INVR 10.0f
#define CAP 1024

// ---------------- scratch (device globals; no allocation) ----------------
__device__ int   g_fps[B * S];
__device__ int   g_grp[B * S * K];
__device__ float g_feat[B * N * CP];   // (B,N,132): fea | raw coords | 0
__device__ float g_Wt[CP * D];         // c-major folded weights, row c = 256 floats
__device__ float g_bias[D];

// ---------------- f32x2 helpers ----------------
__device__ __forceinline__ unsigned long long pack2(float x, float y) {
    unsigned long long r;
    asm("mov.b64 %0, {%1, %2};" : "=l"(r)
        : "r"(__float_as_uint(x)), "r"(__float_as_uint(y)));
    return r;
}
__device__ __forceinline__ void fma2(unsigned long long &a,
                                     unsigned long long x, unsigned long long y) {
    asm("fma.rn.f32x2 %0, %1, %2, %0;" : "+l"(a) : "l"(x), "l"(y));
}
__device__ __forceinline__ void unpack2(unsigned long long v, float &x, float &y) {
    unsigned lo, hi;
    asm("mov.b64 {%0, %1}, %2;" : "=r"(lo), "=r"(hi) : "l"(v));
    x = __uint_as_float(lo); y = __uint_as_float(hi);
}

// ---------------- K0: fold BN into W / bias ----------------
__global__ void fold_kernel(const float* __restrict__ W, const float* __restrict__ bb,
                            const float* __restrict__ gamma, const float* __restrict__ beta,
                            const float* __restrict__ mean, const float* __restrict__ var) {
    int d = threadIdx.x;  // 256 threads
    float sc = gamma[d] * rsqrtf(var[d] + 1e-5f);
    for (int c = 0; c < 131; c++)
        g_Wt[c * D + d] = W[d * 131 + c] * sc;
    g_Wt[131 * D + d] = 0.f;
    g_bias[d] = (bb[d] - mean[d]) * sc + beta[d];
}

// ---------------- K0b: build padded point-major feature tensor ----------------
__global__ void feat_kernel(const float* __restrict__ coor, const float* __restrict__ fea) {
    int i = blockIdx.x * 256 + threadIdx.x;
    if (i >= B * N * CP) return;
    int c = i % CP;
    int bn = i / CP;
    int n = bn % N;
    int b = bn / N;
    float v;
    if (c < C)        v = fea[(b * C + c) * N + n];
    else if (c < 131) v = coor[(b * 3 + (c - C)) * N + n];
    else              v = 0.f;
    g_feat[i] = v;
}

// ---------------- K1: farthest point sampling (1 block / batch) ----------------
__global__ void __launch_bounds__(1024, 1) fps_kernel(const float* __restrict__ coor) {
    int b = blockIdx.x, tid = threadIdx.x;
    const float* base = coor + b * 3 * N;
    float px[8], py[8], pz[8], dist[8];
#pragma unroll
    for (int j = 0; j < 8; j++) {
        int p = j * 1024 + tid;
        px[j] = base[p]; py[j] = base[N + p]; pz[j] = base[2 * N + p];
        dist[j] = 1e10f;
    }
    __shared__ float scx, scy, scz;
    __shared__ unsigned long long swarp[32];
    if (tid == 0) { g_fps[b * S] = 0; scx = base[0]; scy = base[N]; scz = base[2 * N]; }
    __syncthreads();
    int lane = tid & 31, wid = tid >> 5;
    for (int s = 1; s < S; s++) {
        float cx = scx, cy = scy, cz = scz;
        unsigned long long key = 0ull;
#pragma unroll
        for (int j = 0; j < 8; j++) {
            float dx = px[j] - cx, dy = py[j] - cy, dz = pz[j] - cz;
            float d = dx * dx + dy * dy + dz * dz;
            d = fminf(dist[j], d);
            dist[j] = d;
            // monotonic key: dist bits high, (8191 - idx) low -> ties pick smallest idx
            unsigned long long k2 = ((unsigned long long)__float_as_uint(d) << 32)
                                  | (unsigned)(8191 - (j * 1024 + tid));
            key = (k2 > key) ? k2 : key;
        }
#pragma unroll
        for (int off = 16; off; off >>= 1) {
            unsigned long long o = __shfl_down_sync(0xffffffffu, key, off);
            key = (o > key) ? o : key;
        }
        if (lane == 0) swarp[wid] = key;
        __syncthreads();
        if (wid == 0) {
            key = swarp[lane];
#pragma unroll
            for (int off = 16; off; off >>= 1) {
                unsigned long long o = __shfl_down_sync(0xffffffffu, key, off);
                key = (o > key) ? o : key;
            }
            if (lane == 0) {
                int far = 8191 - (int)(key & 0xffffffffull);
                g_fps[b * S + s] = far;
                scx = base[far]; scy = base[N + far]; scz = base[2 * N + far];
            }
        }
        __syncthreads();
    }
}

// ---------------- K2: radius-bounded exact 32-NN (set semantics) ----------------
__global__ void __launch_bounds__(256) knn_kernel(const float* __restrict__ coor,
                                                  float* __restrict__ out_coor) {
    int s = blockIdx.x, b = blockIdx.y, tid = threadIdx.x;
    const float* base = coor + b * 3 * N;
    int ci = g_fps[b * S + s];
    float cx = base[ci], cy = base[N + ci], cz = base[2 * N + ci];
    if (tid < 3) out_coor[(b * 3 + tid) * S + s] = base[tid * N + ci];

    __shared__ int cnt;
    __shared__ float cd[CAP];
    __shared__ int cidx[CAP];
    __shared__ int sel[32];
    if (tid == 0) cnt = 0;
    __syncthreads();

    float cc2 = cx * cx + cy * cy + cz * cz;
    for (int p = tid; p < N; p += 256) {
        float x = base[p], y = base[N + p], z = base[2 * N + p];
        float pp = x * x + y * y + z * z;
        float dt = cx * x + cy * y + cz * z;
        float sq = cc2 + pp - 2.f * dt;   // matches reference's expanded form
        if (sq <= R2) {
            int pos = atomicAdd(&cnt, 1);
            if (pos < CAP) { cd[pos] = sq; cidx[pos] = p; }
        }
    }
    __syncthreads();
    int n = min(cnt, CAP);
    int m = min(n, 32);
    // exact rank selection (total order via (dist, idx)), n is small (~34)
    for (int c = tid; c < n; c += 256) {
        float dc = cd[c]; int ic = cidx[c];
        int r = 0;
        for (int j = 0; j < n; j++) {
            float dj = cd[j]; int ij = cidx[j];
            r += (dj < dc) || (dj == dc && ij < ic);
        }
        if (r < 32) sel[r] = ic;
    }
    __syncthreads();
    if (tid < 32) {
        int gi = (tid < m) ? sel[tid] : sel[0];  // pad with nearest (the centroid itself)
        g_grp[(b * S + s) * K + tid] = gi;
    }
}

// ---------------- K3: fused gather + GEMM(f32x2) + bias/ReLU + max-pool ----------------
__global__ void __launch_bounds__(256, 1) conv_kernel(const float* __restrict__ out_coor,
                                                      float* __restrict__ out_fea) {
    extern __shared__ float smem[];
    float* Wsh = smem;                 // CP*D  = 33792 floats (c-major)
    float* gsh = smem + CP * D;        // CP*K  = 4224 floats  (c-major)
    float* red = gsh + CP * K;         // 8*D   = 2048 floats
    __shared__ int nidx[32];
    __shared__ float cc[3];

    int tid = threadIdx.x;
    for (int i = tid; i < CP * D; i += 256) Wsh[i] = g_Wt[i];
    float biasv = g_bias[tid];

    unsigned sbase;
    asm("{ .reg .u64 t; cvta.to.shared.u64 t, %1; cvt.u32.u64 %0, t; }"
        : "=r"(sbase) : "l"(smem));
    int dt = tid & 31, kt = tid >> 5;            // d-lane (32), k-group (8 x 4k)
    unsigned waddr0 = sbase + (unsigned)(dt * 16);
    const float* gbase = gsh + kt * 4;

    for (int grp = blockIdx.x; grp < B * S; grp += gridDim.x) {
        int b = grp >> 11, s = grp & (S - 1);
        if (tid < 32) nidx[tid] = g_grp[grp * K + tid];
        if (tid < 3)  cc[tid] = out_coor[(b * 3 + tid) * S + s];
        __syncthreads();

        // gather 32 neighbors x 132 channels into c-major gsh
        for (int i = tid; i < 32 * 33; i += 256) {
            int k = i & 31, cq = i >> 5;   // cq in [0,33)
            const float4 v = *(const float4*)(g_feat + (size_t)(b * N + nidx[k]) * CP + cq * 4);
            float4 w = v;
            if (cq == 32) {
                w.x = (v.x - cc[0]) * INVR;
                w.y = (v.y - cc[1]) * INVR;
                w.z = (v.z - cc[2]) * INVR;
                w.w = 0.f;
            }
            int c = cq * 4;
            gsh[(c + 0) * 32 + k] = w.x;
            gsh[(c + 1) * 32 + k] = w.y;
            gsh[(c + 2) * 32 + k] = w.z;
            gsh[(c + 3) * 32 + k] = w.w;
        }
        __syncthreads();

        unsigned long long acc[16];
#pragma unroll
        for (int i = 0; i < 16; i++) acc[i] = 0ull;

#pragma unroll 4
        for (int c = 0; c < CP; c++) {
            float4 g4 = *(const float4*)(gbase + c * 32);
            unsigned long long gg0 = pack2(g4.x, g4.x);
            unsigned long long gg1 = pack2(g4.y, g4.y);
            unsigned long long gg2 = pack2(g4.z, g4.z);
            unsigned long long gg3 = pack2(g4.w, g4.w);
            unsigned long long w0, w1, w2, w3;
            unsigned a0 = waddr0 + (unsigned)(c * (D * 4));
            asm volatile("ld.shared.v2.b64 {%0,%1}, [%2];" : "=l"(w0), "=l"(w1) : "r"(a0));
            asm volatile("ld.shared.v2.b64 {%0,%1}, [%2];" : "=l"(w2), "=l"(w3) : "r"(a0 + 512u));
            fma2(acc[0],  gg0, w0); fma2(acc[1],  gg0, w1); fma2(acc[2],  gg0, w2); fma2(acc[3],  gg0, w3);
            fma2(acc[4],  gg1, w0); fma2(acc[5],  gg1, w1); fma2(acc[6],  gg1, w2); fma2(acc[7],  gg1, w3);
            fma2(acc[8],  gg2, w0); fma2(acc[9],  gg2, w1); fma2(acc[10], gg2, w2); fma2(acc[11], gg2, w3);
            fma2(acc[12], gg3, w0); fma2(acc[13], gg3, w1); fma2(acc[14], gg3, w2); fma2(acc[15], gg3, w3);
        }

        // local max over this thread's 4 k's
        float mx[8];
#pragma unroll
        for (int l = 0; l < 8; l++) mx[l] = -1e30f;
#pragma unroll
        for (int ki = 0; ki < 4; ki++) {
#pragma unroll
            for (int dj = 0; dj < 4; dj++) {
                float a, bv; unpack2(acc[ki * 4 + dj], a, bv);
                mx[dj * 2]     = fmaxf(mx[dj * 2], a);
                mx[dj * 2 + 1] = fmaxf(mx[dj * 2 + 1], bv);
            }
        }
#pragma unroll
        for (int l = 0; l < 4; l++) {
            red[kt * D + dt * 4 + l]       = mx[l];
            red[kt * D + 128 + dt * 4 + l] = mx[4 + l];
        }
        __syncthreads();

        // cross-k-group max, bias, relu, store
        {
            float v = red[tid];
#pragma unroll
            for (int q = 1; q < 8; q++) v = fmaxf(v, red[q * D + tid]);
            float o = v + biasv;
            o = o > 0.f ? o : 0.f;
            out_fea[((size_t)b * D + tid) * S + s] = o;
        }
        __syncthreads();
    }
}

// ---------------- launch ----------------
extern "C" void kernel_launch(void* const* d_in, const int* in_sizes, int n_in,
                              void* d_out, int out_size) {
    const float* coor  = (const float*)d_in[0];
    const float* fea   = (const float*)d_in[1];
    const float* W     = (const float*)d_in[2];
    const float* bb    = (const float*)d_in[3];
    const float* gamma = (const float*)d_in[4];
    const float* beta  = (const float*)d_in[5];
    const float* mean  = (const float*)d_in[6];
    const float* var   = (const float*)d_in[7];

    float* out      = (float*)d_out;
    float* out_coor = out;              // (B,3,S)
    float* out_fea  = out + B * 3 * S;  // (B,2C,S)

    fold_kernel<<<1, 256>>>(W, bb, gamma, beta, mean, var);
    feat_kernel<<<(B * N * CP + 255) / 256, 256>>>(coor, fea);
    fps_kernel<<<B, 1024>>>(coor);
    knn_kernel<<<dim3(S, B), 256>>>(coor, out_coor);

    const int smem_bytes = (CP * D + CP * K + 8 * D) * 4;  // 160256 B
    cudaFuncSetAttribute(conv_kernel, cudaFuncAttributeMaxDynamicSharedMemorySize, smem_bytes);
    conv_kernel<<<148, 256, smem_bytes>>>(out_coor, out_fea);
}

// round 2
// speedup vs baseline: 1.2574x; 1.2574x over previous
#include <cuda_runtime.h>

#define B 4
#define N 8192
#define C 128
#define S 2048
#define K 32
#define D 256      // 2C
#define CP 132     // C+3 padded to 132 (mult of 4)
#define R2 0.01f
#define CAP 1024

// ---------------- scratch (device globals; no allocation) ----------------
__device__ int   g_fps[B * S];
__device__ int   g_grp[B * S * K];
__device__ float g_feat[B * N * CP];   // (B,N,132): fea | raw coords | 0
__device__ float g_Wt[CP * D];         // c-major folded weights (coord rows pre-scaled by 10)
__device__ float g_bias[D];

// ---------------- helpers ----------------
__device__ __forceinline__ unsigned long long pack2(float x, float y) {
    unsigned long long r;
    asm("mov.b64 %0, {%1, %2};" : "=l"(r)
        : "r"(__float_as_uint(x)), "r"(__float_as_uint(y)));
    return r;
}
__device__ __forceinline__ void fma2(unsigned long long &a,
                                     unsigned long long x, unsigned long long y) {
    asm("fma.rn.f32x2 %0, %1, %2, %0;" : "+l"(a) : "l"(x), "l"(y));
}
__device__ __forceinline__ void unpack2(unsigned long long v, float &x, float &y) {
    unsigned lo, hi;
    asm("mov.b64 {%0, %1}, %2;" : "=r"(lo), "=r"(hi) : "l"(v));
    x = __uint_as_float(lo); y = __uint_as_float(hi);
}
__device__ __forceinline__ unsigned redux_max_u32(unsigned v) {
    unsigned r;
    asm("redux.sync.max.u32 %0, %1, 0xffffffff;" : "=r"(r) : "r"(v));
    return r;
}
__device__ __forceinline__ unsigned redux_min_u32(unsigned v) {
    unsigned r;
    asm("redux.sync.min.u32 %0, %1, 0xffffffff;" : "=r"(r) : "r"(v));
    return r;
}

// ---------------- K0: fold BN into W / bias; scale coord rows by 1/RADIUS ----------------
__global__ void fold_kernel(const float* __restrict__ W, const float* __restrict__ bb,
                            const float* __restrict__ gamma, const float* __restrict__ beta,
                            const float* __restrict__ mean, const float* __restrict__ var) {
    int d = threadIdx.x;  // 256 threads
    float sc = gamma[d] * rsqrtf(var[d] + 1e-5f);
    for (int c = 0; c < 128; c++)
        g_Wt[c * D + d] = W[d * 131 + c] * sc;
    for (int c = 128; c < 131; c++)
        g_Wt[c * D + d] = W[d * 131 + c] * sc * 10.0f;   // fold 1/RADIUS
    g_Wt[131 * D + d] = 0.f;
    g_bias[d] = (bb[d] - mean[d]) * sc + beta[d];
}

// ---------------- K0b: build padded point-major feature tensor ----------------
__global__ void feat_kernel(const float* __restrict__ coor, const float* __restrict__ fea) {
    int i = blockIdx.x * 256 + threadIdx.x;
    if (i >= B * N * CP) return;
    int c = i % CP;
    int bn = i / CP;
    int n = bn % N;
    int b = bn / N;
    float v;
    if (c < C)        v = fea[(b * C + c) * N + n];
    else if (c < 131) v = coor[(b * 3 + (c - C)) * N + n];
    else              v = 0.f;
    g_feat[i] = v;
}

// ---------------- K1: farthest point sampling (1 block / batch, redux.sync) ----------------
__global__ void __launch_bounds__(1024, 1) fps_kernel(const float* __restrict__ coor) {
    int b = blockIdx.x, tid = threadIdx.x;
    const float* base = coor + b * 3 * N;
    float px[8], py[8], pz[8], dist[8];
#pragma unroll
    for (int j = 0; j < 8; j++) {
        int p = j * 1024 + tid;
        px[j] = base[p]; py[j] = base[N + p]; pz[j] = base[2 * N + p];
        dist[j] = 1e10f;
    }
    __shared__ unsigned sM[2][32];
    __shared__ unsigned sI[2][32];
    if (tid == 0) g_fps[b * S] = 0;
    int lane = tid & 31, wid = tid >> 5;
    // current centroid in registers (all threads, broadcast LDG)
    float cx = base[0], cy = base[N], cz = base[2 * N];
    __syncthreads();

    for (int s = 1; s < S; s++) {
        // update min-dists vs current centroid; local argmax (first-wins = min idx)
        float bd = -1.0f; int bidx = 0;
#pragma unroll
        for (int j = 0; j < 8; j++) {
            float dx = px[j] - cx, dy = py[j] - cy, dz = pz[j] - cz;
            float d = dx * dx + dy * dy + dz * dz;   // same expression as round 1
            d = fminf(dist[j], d);
            dist[j] = d;
            if (d > bd) { bd = d; bidx = j * 1024 + tid; }
        }
        // warp stage: max dist bits, then min index among ties (exact)
        unsigned db = __float_as_uint(bd);
        unsigned mb = redux_max_u32(db);
        unsigned cand = (db == mb) ? (unsigned)bidx : 0xffffffffu;
        unsigned im = redux_min_u32(cand);
        int buf = s & 1;
        if (lane == 0) { sM[buf][wid] = mb; sI[buf][wid] = im; }
        __syncthreads();
        // block stage: every warp reduces all 32 warp results (no 2nd barrier)
        unsigned m2 = sM[buf][lane];
        unsigned i2 = sI[buf][lane];
        unsigned MB = redux_max_u32(m2);
        unsigned c2 = (m2 == MB) ? i2 : 0xffffffffu;
        unsigned I = redux_min_u32(c2);
        if (tid == 0) g_fps[b * S + s] = (int)I;
        cx = __ldg(base + I); cy = __ldg(base + N + I); cz = __ldg(base + 2 * N + I);
    }
}

// ---------------- K2: radius-bounded exact 32-NN (set semantics) ----------------
__global__ void __launch_bounds__(256) knn_kernel(const float* __restrict__ coor,
                                                  float* __restrict__ out_coor) {
    int s = blockIdx.x, b = blockIdx.y, tid = threadIdx.x;
    const float* base = coor + b * 3 * N;
    int ci = g_fps[b * S + s];
    float cx = base[ci], cy = base[N + ci], cz = base[2 * N + ci];
    if (tid < 3) out_coor[(b * 3 + tid) * S + s] = base[tid * N + ci];

    __shared__ int cnt;
    __shared__ float cd[CAP];
    __shared__ int cidx[CAP];
    __shared__ int sel[32];
    if (tid == 0) cnt = 0;
    __syncthreads();

    float cc2 = cx * cx + cy * cy + cz * cz;
    for (int p = tid; p < N; p += 256) {
        float x = base[p], y = base[N + p], z = base[2 * N + p];
        float pp = x * x + y * y + z * z;
        float dt = cx * x + cy * y + cz * z;
        float sq = cc2 + pp - 2.f * dt;   // matches reference's expanded form
        if (sq <= R2) {
            int pos = atomicAdd(&cnt, 1);
            if (pos < CAP) { cd[pos] = sq; cidx[pos] = p; }
        }
    }
    __syncthreads();
    int n = min(cnt, CAP);
    int m = min(n, 32);
    // exact rank selection (total order via (dist, idx)), n is small (~34)
    for (int c = tid; c < n; c += 256) {
        float dc = cd[c]; int ic = cidx[c];
        int r = 0;
        for (int j = 0; j < n; j++) {
            float dj = cd[j]; int ij = cidx[j];
            r += (dj < dc) || (dj == dc && ij < ic);
        }
        if (r < 32) sel[r] = ic;
    }
    __syncthreads();
    if (tid < 32) {
        int gi = (tid < m) ? sel[tid] : sel[0];  // pad with nearest (the centroid itself)
        g_grp[(b * S + s) * K + tid] = gi;
    }
}

// ---------------- K3: fused gather + GEMM(f32x2, 4d x 8k tile) + bias/ReLU + max-pool ---
__global__ void __launch_bounds__(256, 1) conv_kernel(const float* __restrict__ out_coor,
                                                      float* __restrict__ out_fea) {
    extern __shared__ float smem[];
    float* Wsh = smem;                 // CP*D  = 33792 floats (c-major)
    float* gsh = smem + CP * D;        // CP*K  = 4224 floats  (c-major, raw features)
    float* red = gsh + CP * K;         // 4*D   = 1024 floats
    __shared__ int nidx[32];
    __shared__ float cc[3];

    int tid = threadIdx.x;
    for (int i = tid; i < CP * D; i += 256) Wsh[i] = g_Wt[i];
    float biasv = g_bias[tid];

    unsigned sbase;
    asm("{ .reg .u64 t; cvta.to.shared.u64 t, %1; cvt.u32.u64 %0, t; }"
        : "=r"(sbase) : "l"(smem));
    int dt = tid & 63, kt = tid >> 6;              // 64 d-lanes x 4 k-groups (8k each)
    unsigned waddr0 = sbase + (unsigned)(dt * 16); // 16B of W per thread per c
    const float* gb = gsh + kt * 8;
    __syncthreads();

    for (int grp = blockIdx.x; grp < B * S; grp += gridDim.x) {
        int b = grp >> 11, s = grp & (S - 1);
        if (tid < 32) nidx[tid] = g_grp[grp * K + tid];
        if (tid < 3)  cc[tid] = out_coor[(b * 3 + tid) * S + s];
        __syncthreads();

        // gather 32 neighbors x 132 channels into c-major gsh (pure copy)
        for (int i = tid; i < 32 * 33; i += 256) {
            int k = i & 31, cq = i >> 5;
            const float4 v = *(const float4*)(g_feat + (size_t)(b * N + nidx[k]) * CP + cq * 4);
            int c = cq * 4;
            gsh[(c + 0) * 32 + k] = v.x;
            gsh[(c + 1) * 32 + k] = v.y;
            gsh[(c + 2) * 32 + k] = v.z;
            gsh[(c + 3) * 32 + k] = v.w;
        }
        __syncthreads();

        unsigned long long acc[16];   // [k=8][dpair=2]
#pragma unroll
        for (int i = 0; i < 16; i++) acc[i] = 0ull;

#pragma unroll 2
        for (int c = 0; c < CP; c++) {
            unsigned long long w0, w1;
            unsigned a0 = waddr0 + (unsigned)(c * (D * 4));
            asm volatile("ld.shared.v2.b64 {%0,%1}, [%2];" : "=l"(w0), "=l"(w1) : "r"(a0));
            float4 ga = *(const float4*)(gb + c * 32);      // k = kt*8 + 0..3 (broadcast)
            float4 gc = *(const float4*)(gb + c * 32 + 4);  // k = kt*8 + 4..7 (broadcast)
            unsigned long long g0 = pack2(ga.x, ga.x), g1 = pack2(ga.y, ga.y);
            unsigned long long g2 = pack2(ga.z, ga.z), g3 = pack2(ga.w, ga.w);
            unsigned long long g4 = pack2(gc.x, gc.x), g5 = pack2(gc.y, gc.y);
            unsigned long long g6 = pack2(gc.z, gc.z), g7 = pack2(gc.w, gc.w);
            fma2(acc[0],  g0, w0); fma2(acc[1],  g0, w1);
            fma2(acc[2],  g1, w0); fma2(acc[3],  g1, w1);
            fma2(acc[4],  g2, w0); fma2(acc[5],  g2, w1);
            fma2(acc[6],  g3, w0); fma2(acc[7],  g3, w1);
            fma2(acc[8],  g4, w0); fma2(acc[9],  g4, w1);
            fma2(acc[10], g5, w0); fma2(acc[11], g5, w1);
            fma2(acc[12], g6, w0); fma2(acc[13], g6, w1);
            fma2(acc[14], g7, w0); fma2(acc[15], g7, w1);
        }

        // local max over this thread's 8 k's (4 d values: dt*4 .. dt*4+3)
        float mx[4];
#pragma unroll
        for (int l = 0; l < 4; l++) mx[l] = -1e30f;
#pragma unroll
        for (int ki = 0; ki < 8; ki++) {
            float a, bv;
            unpack2(acc[ki * 2 + 0], a, bv);
            mx[0] = fmaxf(mx[0], a); mx[1] = fmaxf(mx[1], bv);
            unpack2(acc[ki * 2 + 1], a, bv);
            mx[2] = fmaxf(mx[2], a); mx[3] = fmaxf(mx[3], bv);
        }
#pragma unroll
        for (int l = 0; l < 4; l++)
            red[kt * D + dt * 4 + l] = mx[l];
        __syncthreads();

        // cross-k-group max, coord-fold adjustment, bias, relu, store (d = tid)
        {
            float v = red[tid];
#pragma unroll
            for (int q = 1; q < 4; q++) v = fmaxf(v, red[q * D + tid]);
            float adj = Wsh[128 * D + tid] * cc[0]
                      + Wsh[129 * D + tid] * cc[1]
                      + Wsh[130 * D + tid] * cc[2];
            float o = v - adj + biasv;
            o = o > 0.f ? o : 0.f;
            out_fea[((size_t)b * D + tid) * S + s] = o;
        }
        __syncthreads();
    }
}

// ---------------- launch ----------------
extern "C" void kernel_launch(void* const* d_in, const int* in_sizes, int n_in,
                              void* d_out, int out_size) {
    const float* coor  = (const float*)d_in[0];
    const float* fea   = (const float*)d_in[1];
    const float* W     = (const float*)d_in[2];
    const float* bb    = (const float*)d_in[3];
    const float* gamma = (const float*)d_in[4];
    const float* beta  = (const float*)d_in[5];
    const float* mean  = (const float*)d_in[6];
    const float* var   = (const float*)d_in[7];

    float* out      = (float*)d_out;
    float* out_coor = out;              // (B,3,S)
    float* out_fea  = out + B * 3 * S;  // (B,2C,S)

    fold_kernel<<<1, 256>>>(W, bb, gamma, beta, mean, var);
    feat_kernel<<<(B * N * CP + 255) / 256, 256>>>(coor, fea);
    fps_kernel<<<B, 1024>>>(coor);
    knn_kernel<<<dim3(S, B), 256>>>(coor, out_coor);

    const int smem_bytes = (CP * D + CP * K + 4 * D) * 4;  // 156160 B
    cudaFuncSetAttribute(conv_kernel, cudaFuncAttributeMaxDynamicSharedMemorySize, smem_bytes);
    conv_kernel<<<148, 256, smem_bytes>>>(out_coor, out_fea);
}

// round 3
// speedup vs baseline: 1.4387x; 1.1442x over previous
#include <cuda_runtime.h>

#define B 4
#define N 8192
#define C 128
#define S 2048
#define K 32
#define D 256      // 2C
#define CP 132     // C+3 padded to 132 (mult of 4)
#define R2 0.01f
#define CAP 256
#define SPB 4      // centroids per knn block

// ---------------- scratch (device globals; no allocation) ----------------
__device__ int   g_fps[B * S];
__device__ int   g_grp[B * S * K];
__device__ float g_feat[B * N * CP];   // (B,N,132): fea | raw coords | 0
__device__ float g_Wt[CP * D];         // c-major folded weights (coord rows pre-scaled by 10)
__device__ float g_bias[D];

// ---------------- helpers ----------------
__device__ __forceinline__ unsigned long long pack2(float x, float y) {
    unsigned long long r;
    asm("mov.b64 %0, {%1, %2};" : "=l"(r)
        : "r"(__float_as_uint(x)), "r"(__float_as_uint(y)));
    return r;
}
__device__ __forceinline__ void fma2(unsigned long long &a,
                                     unsigned long long x, unsigned long long y) {
    asm("fma.rn.f32x2 %0, %1, %2, %0;" : "+l"(a) : "l"(x), "l"(y));
}
__device__ __forceinline__ unsigned long long add2(unsigned long long a,
                                                   unsigned long long b) {
    unsigned long long r;
    asm("add.rn.f32x2 %0, %1, %2;" : "=l"(r) : "l"(a), "l"(b));
    return r;
}
__device__ __forceinline__ unsigned long long mul2(unsigned long long a,
                                                   unsigned long long b) {
    unsigned long long r;
    asm("mul.rn.f32x2 %0, %1, %2;" : "=l"(r) : "l"(a), "l"(b));
    return r;
}
__device__ __forceinline__ void unpack2(unsigned long long v, float &x, float &y) {
    unsigned lo, hi;
    asm("mov.b64 {%0, %1}, %2;" : "=r"(lo), "=r"(hi) : "l"(v));
    x = __uint_as_float(lo); y = __uint_as_float(hi);
}
__device__ __forceinline__ unsigned redux_max_u32(unsigned v) {
    unsigned r;
    asm("redux.sync.max.u32 %0, %1, 0xffffffff;" : "=r"(r) : "r"(v));
    return r;
}
__device__ __forceinline__ unsigned redux_min_u32(unsigned v) {
    unsigned r;
    asm("redux.sync.min.u32 %0, %1, 0xffffffff;" : "=r"(r) : "r"(v));
    return r;
}

// ---------------- K0: fold BN into W / bias; scale coord rows by 1/RADIUS ----------------
__global__ void fold_kernel(const float* __restrict__ W, const float* __restrict__ bb,
                            const float* __restrict__ gamma, const float* __restrict__ beta,
                            const float* __restrict__ mean, const float* __restrict__ var) {
    int d = threadIdx.x;  // 256 threads
    float sc = gamma[d] * rsqrtf(var[d] + 1e-5f);
    for (int c = 0; c < 128; c++)
        g_Wt[c * D + d] = W[d * 131 + c] * sc;
    for (int c = 128; c < 131; c++)
        g_Wt[c * D + d] = W[d * 131 + c] * sc * 10.0f;   // fold 1/RADIUS
    g_Wt[131 * D + d] = 0.f;
    g_bias[d] = (bb[d] - mean[d]) * sc + beta[d];
}

// ---------------- K0b: build padded point-major feature tensor ----------------
__global__ void feat_kernel(const float* __restrict__ coor, const float* __restrict__ fea) {
    int i = blockIdx.x * 256 + threadIdx.x;
    if (i >= B * N * CP) return;
    int c = i % CP;
    int bn = i / CP;
    int n = bn % N;
    int b = bn / N;
    float v;
    if (c < C)        v = fea[(b * C + c) * N + n];
    else if (c < 131) v = coor[(b * 3 + (c - C)) * N + n];
    else              v = 0.f;
    g_feat[i] = v;
}

// ---------------- K1: farthest point sampling (1 block / batch, f32x2 update) ----------
__global__ void __launch_bounds__(1024, 1) fps_kernel(const float* __restrict__ coor) {
    int b = blockIdx.x, tid = threadIdx.x;
    const float* base = coor + b * 3 * N;
    unsigned long long px2[4], py2[4], pz2[4];
    float dist[8];
#pragma unroll
    for (int q = 0; q < 4; q++) {
        int p0 = (2 * q) * 1024 + tid, p1 = (2 * q + 1) * 1024 + tid;
        px2[q] = pack2(base[p0],         base[p1]);
        py2[q] = pack2(base[N + p0],     base[N + p1]);
        pz2[q] = pack2(base[2 * N + p0], base[2 * N + p1]);
    }
#pragma unroll
    for (int i = 0; i < 8; i++) dist[i] = 1e10f;

    __shared__ unsigned sM[2][32];
    __shared__ unsigned sI[2][32];
    if (tid == 0) g_fps[b * S] = 0;
    int lane = tid & 31, wid = tid >> 5;
    float cx = base[0], cy = base[N], cz = base[2 * N];
    __syncthreads();

    for (int s = 1; s < S; s++) {
        unsigned long long ncx = pack2(-cx, -cx);
        unsigned long long ncy = pack2(-cy, -cy);
        unsigned long long ncz = pack2(-cz, -cz);
        // packed distance update: identical rounding to scalar
        // (p + (-c)) == (p - c);  mul2/fma2/fma2 == dx*dx; fma(dy,dy,.); fma(dz,dz,.)
#pragma unroll
        for (int q = 0; q < 4; q++) {
            unsigned long long dx = add2(px2[q], ncx);
            unsigned long long dy = add2(py2[q], ncy);
            unsigned long long dz = add2(pz2[q], ncz);
            unsigned long long d2 = mul2(dx, dx);
            fma2(d2, dy, dy);
            fma2(d2, dz, dz);
            float dlo, dhi; unpack2(d2, dlo, dhi);
            dist[2 * q]     = fminf(dist[2 * q],     dlo);
            dist[2 * q + 1] = fminf(dist[2 * q + 1], dhi);
        }
        // scalar argmax over 8, strict > keeps lowest j (ties -> min idx)
        float bd = dist[0]; int bj = 0;
#pragma unroll
        for (int j = 1; j < 8; j++)
            if (dist[j] > bd) { bd = dist[j]; bj = j; }
        int bidx = (bj << 10) | tid;

        // warp stage: max dist bits, then min index among ties (exact)
        unsigned db = __float_as_uint(bd);    // all dists >= 0: bit order == float order
        unsigned mb = redux_max_u32(db);
        unsigned cand = (db == mb) ? (unsigned)bidx : 0xffffffffu;
        unsigned im = redux_min_u32(cand);
        int buf = s & 1;
        if (lane == 0) { sM[buf][wid] = mb; sI[buf][wid] = im; }
        __syncthreads();
        // block stage: every warp reduces all 32 warp results (no 2nd barrier)
        unsigned m2 = sM[buf][lane];
        unsigned i2 = sI[buf][lane];
        unsigned MB = redux_max_u32(m2);
        unsigned c2 = (m2 == MB) ? i2 : 0xffffffffu;
        unsigned I = redux_min_u32(c2);
        if (tid == 0) g_fps[b * S + s] = (int)I;
        cx = __ldg(base + I); cy = __ldg(base + N + I); cz = __ldg(base + 2 * N + I);
    }
}

// ---------------- K2: radius-bounded exact 32-NN, 4 centroids / block ----------------
__global__ void __launch_bounds__(256) knn_kernel(const float* __restrict__ coor,
                                                  float* __restrict__ out_coor) {
    int s0 = blockIdx.x * SPB, b = blockIdx.y, tid = threadIdx.x;
    const float* base = coor + b * 3 * N;

    __shared__ int   cnt[SPB];
    __shared__ float cd[SPB][CAP];
    __shared__ int   cidx[SPB][CAP];
    __shared__ int   sel[SPB][32];

    float cx[SPB], cy[SPB], cz[SPB], cc2[SPB];
#pragma unroll
    for (int u = 0; u < SPB; u++) {
        int ci = g_fps[b * S + s0 + u];
        cx[u] = __ldg(base + ci);
        cy[u] = __ldg(base + N + ci);
        cz[u] = __ldg(base + 2 * N + ci);
        cc2[u] = cx[u] * cx[u] + cy[u] * cy[u] + cz[u] * cz[u];
        if (tid < 3) {
            float v = (tid == 0) ? cx[u] : (tid == 1) ? cy[u] : cz[u];
            out_coor[(b * 3 + tid) * S + (s0 + u)] = v;
        }
    }
    if (tid < SPB) cnt[tid] = 0;
    __syncthreads();

    for (int p = tid; p < N; p += 256) {
        float x = base[p], y = base[N + p], z = base[2 * N + p];
        float pp = x * x + y * y + z * z;
#pragma unroll
        for (int u = 0; u < SPB; u++) {
            float dt = cx[u] * x + cy[u] * y + cz[u] * z;
            float sq = cc2[u] + pp - 2.f * dt;   // matches reference's expanded form
            if (sq <= R2) {
                int pos = atomicAdd(&cnt[u], 1);
                if (pos < CAP) { cd[u][pos] = sq; cidx[u][pos] = p; }
            }
        }
    }
    __syncthreads();

#pragma unroll
    for (int u = 0; u < SPB; u++) {
        int n = min(cnt[u], CAP);
        // exact rank selection (total order via (dist, idx)), n is small (~34)
        for (int c = tid; c < n; c += 256) {
            float dc = cd[u][c]; int ic = cidx[u][c];
            int r = 0;
            for (int j = 0; j < n; j++) {
                float dj = cd[u][j]; int ij = cidx[u][j];
                r += (dj < dc) || (dj == dc && ij < ic);
            }
            if (r < 32) sel[u][r] = ic;
        }
    }
    __syncthreads();
    if (tid < 32) {
#pragma unroll
        for (int u = 0; u < SPB; u++) {
            int m = min(cnt[u], 32);
            int gi = (tid < m) ? sel[u][tid] : sel[u][0];  // pad with nearest
            g_grp[(b * S + s0 + u) * K + tid] = gi;
        }
    }
}

// ---------------- K3: fused gather + GEMM(f32x2, 4d x 8k tile) + bias/ReLU + max-pool ---
__global__ void __launch_bounds__(256, 1) conv_kernel(const float* __restrict__ out_coor,
                                                      float* __restrict__ out_fea) {
    extern __shared__ float smem[];
    float* Wsh = smem;                 // CP*D  = 33792 floats (c-major)
    float* gsh = smem + CP * D;        // CP*K  = 4224 floats  (c-major, raw features)
    float* red = gsh + CP * K;         // 4*D   = 1024 floats
    __shared__ int nidx[32];
    __shared__ float cc[3];

    int tid = threadIdx.x;
    for (int i = tid; i < CP * D; i += 256) Wsh[i] = g_Wt[i];
    float biasv = g_bias[tid];

    unsigned sbase;
    asm("{ .reg .u64 t; cvta.to.shared.u64 t, %1; cvt.u32.u64 %0, t; }"
        : "=r"(sbase) : "l"(smem));
    int dt = tid & 63, kt = tid >> 6;              // 64 d-lanes x 4 k-groups (8k each)
    unsigned waddr0 = sbase + (unsigned)(dt * 16); // 16B of W per thread per c
    const float* gb = gsh + kt * 8;
    __syncthreads();

    for (int grp = blockIdx.x; grp < B * S; grp += gridDim.x) {
        int b = grp >> 11, s = grp & (S - 1);
        if (tid < 32) nidx[tid] = g_grp[grp * K + tid];
        if (tid < 3)  cc[tid] = out_coor[(b * 3 + tid) * S + s];
        __syncthreads();

        // gather 32 neighbors x 132 channels into c-major gsh (pure copy)
        for (int i = tid; i < 32 * 33; i += 256) {
            int k = i & 31, cq = i >> 5;
            const float4 v = *(const float4*)(g_feat + (size_t)(b * N + nidx[k]) * CP + cq * 4);
            int c = cq * 4;
            gsh[(c + 0) * 32 + k] = v.x;
            gsh[(c + 1) * 32 + k] = v.y;
            gsh[(c + 2) * 32 + k] = v.z;
            gsh[(c + 3) * 32 + k] = v.w;
        }
        __syncthreads();

        unsigned long long acc[16];   // [k=8][dpair=2]
#pragma unroll
        for (int i = 0; i < 16; i++) acc[i] = 0ull;

#pragma unroll 2
        for (int c = 0; c < CP; c++) {
            unsigned long long w0, w1;
            unsigned a0 = waddr0 + (unsigned)(c * (D * 4));
            asm volatile("ld.shared.v2.b64 {%0,%1}, [%2];" : "=l"(w0), "=l"(w1) : "r"(a0));
            float4 ga = *(const float4*)(gb + c * 32);      // k = kt*8 + 0..3 (broadcast)
            float4 gc = *(const float4*)(gb + c * 32 + 4);  // k = kt*8 + 4..7 (broadcast)
            unsigned long long g0 = pack2(ga.x, ga.x), g1 = pack2(ga.y, ga.y);
            unsigned long long g2 = pack2(ga.z, ga.z), g3 = pack2(ga.w, ga.w);
            unsigned long long g4 = pack2(gc.x, gc.x), g5 = pack2(gc.y, gc.y);
            unsigned long long g6 = pack2(gc.z, gc.z), g7 = pack2(gc.w, gc.w);
            fma2(acc[0],  g0, w0); fma2(acc[1],  g0, w1);
            fma2(acc[2],  g1, w0); fma2(acc[3],  g1, w1);
            fma2(acc[4],  g2, w0); fma2(acc[5],  g2, w1);
            fma2(acc[6],  g3, w0); fma2(acc[7],  g3, w1);
            fma2(acc[8],  g4, w0); fma2(acc[9],  g4, w1);
            fma2(acc[10], g5, w0); fma2(acc[11], g5, w1);
            fma2(acc[12], g6, w0); fma2(acc[13], g6, w1);
            fma2(acc[14], g7, w0); fma2(acc[15], g7, w1);
        }

        // local max over this thread's 8 k's (4 d values: dt*4 .. dt*4+3)
        float mx[4];
#pragma unroll
        for (int l = 0; l < 4; l++) mx[l] = -1e30f;
#pragma unroll
        for (int ki = 0; ki < 8; ki++) {
            float a, bv;
            unpack2(acc[ki * 2 + 0], a, bv);
            mx[0] = fmaxf(mx[0], a); mx[1] = fmaxf(mx[1], bv);
            unpack2(acc[ki * 2 + 1], a, bv);
            mx[2] = fmaxf(mx[2], a); mx[3] = fmaxf(mx[3], bv);
        }
#pragma unroll
        for (int l = 0; l < 4; l++)
            red[kt * D + dt * 4 + l] = mx[l];
        __syncthreads();

        // cross-k-group max, coord-fold adjustment, bias, relu, store (d = tid)
        {
            float v = red[tid];
#pragma unroll
            for (int q = 1; q < 4; q++) v = fmaxf(v, red[q * D + tid]);
            float adj = Wsh[128 * D + tid] * cc[0]
                      + Wsh[129 * D + tid] * cc[1]
                      + Wsh[130 * D + tid] * cc[2];
            float o = v - adj + biasv;
            o = o > 0.f ? o : 0.f;
            out_fea[((size_t)b * D + tid) * S + s] = o;
        }
        __syncthreads();
    }
}

// ---------------- launch ----------------
extern "C" void kernel_launch(void* const* d_in, const int* in_sizes, int n_in,
                              void* d_out, int out_size) {
    const float* coor  = (const float*)d_in[0];
    const float* fea   = (const float*)d_in[1];
    const float* W     = (const float*)d_in[2];
    const float* bb    = (const float*)d_in[3];
    const float* gamma = (const float*)d_in[4];
    const float* beta  = (const float*)d_in[5];
    const float* mean  = (const float*)d_in[6];
    const float* var   = (const float*)d_in[7];

    float* out      = (float*)d_out;
    float* out_coor = out;              // (B,3,S)
    float* out_fea  = out + B * 3 * S;  // (B,2C,S)

    fold_kernel<<<1, 256>>>(W, bb, gamma, beta, mean, var);
    feat_kernel<<<(B * N * CP + 255) / 256, 256>>>(coor, fea);
    fps_kernel<<<B, 1024>>>(coor);
    knn_kernel<<<dim3(S / SPB, B), 256>>>(coor, out_coor);

    const int smem_bytes = (CP * D + CP * K + 4 * D) * 4;  // 156160 B
    cudaFuncSetAttribute(conv_kernel, cudaFuncAttributeMaxDynamicSharedMemorySize, smem_bytes);
    conv_kernel<<<148, 256, smem_bytes>>>(out_coor, out_fea);
}

// round 4
// speedup vs baseline: 1.7696x; 1.2301x over previous
#include <cuda_runtime.h>

#define B 4
#define N 8192
#define C 128
#define S 2048
#define K 32
#define D 256      // 2C
#define CP 132     // C+3 padded
#define R2 0.01f
#define CAP 256
#define NWORK 144
#define NCTA 148

// ---------------- scratch (device globals; no allocation) ----------------
__device__ int            g_fps[B * S];
__device__ volatile int   g_prog[B];     // fps progress per batch (#indices ready)
__device__ volatile int   g_sync;        // worker pre-phase barrier counter
__device__ float          g_feat[B * N * CP];
__device__ float          g_Wt[CP * D];
__device__ float          g_bias[D];

// ---------------- helpers ----------------
__device__ __forceinline__ unsigned long long pack2(float x, float y) {
    unsigned long long r;
    asm("mov.b64 %0, {%1, %2};" : "=l"(r)
        : "r"(__float_as_uint(x)), "r"(__float_as_uint(y)));
    return r;
}
__device__ __forceinline__ void fma2(unsigned long long &a,
                                     unsigned long long x, unsigned long long y) {
    asm("fma.rn.f32x2 %0, %1, %2, %0;" : "+l"(a) : "l"(x), "l"(y));
}
__device__ __forceinline__ unsigned long long add2(unsigned long long a,
                                                   unsigned long long b) {
    unsigned long long r;
    asm("add.rn.f32x2 %0, %1, %2;" : "=l"(r) : "l"(a), "l"(b));
    return r;
}
__device__ __forceinline__ unsigned long long mul2(unsigned long long a,
                                                   unsigned long long b) {
    unsigned long long r;
    asm("mul.rn.f32x2 %0, %1, %2;" : "=l"(r) : "l"(a), "l"(b));
    return r;
}
__device__ __forceinline__ void unpack2(unsigned long long v, float &x, float &y) {
    unsigned lo, hi;
    asm("mov.b64 {%0, %1}, %2;" : "=r"(lo), "=r"(hi) : "l"(v));
    x = __uint_as_float(lo); y = __uint_as_float(hi);
}
__device__ __forceinline__ unsigned redux_max_u32(unsigned v) {
    unsigned r;
    asm("redux.sync.max.u32 %0, %1, 0xffffffff;" : "=r"(r) : "r"(v));
    return r;
}
__device__ __forceinline__ unsigned redux_min_u32(unsigned v) {
    unsigned r;
    asm("redux.sync.min.u32 %0, %1, 0xffffffff;" : "=r"(r) : "r"(v));
    return r;
}
#define WBAR() asm volatile("bar.sync 1, 256;" ::: "memory")

// ---------------- init: reset cross-CTA state each invocation ----------------
__global__ void init_kernel() {
    if (threadIdx.x < B) g_prog[threadIdx.x] = 0;
    if (threadIdx.x == 0) g_sync = 0;
}

// =======================  FPS (producer) path  ==========================
__device__ void fps_block(const float* __restrict__ coor, int b, int tid) {
    const float* base = coor + b * 3 * N;
    unsigned long long px2[8], py2[8], pz2[8];
    float dist[16];
#pragma unroll
    for (int q = 0; q < 8; q++) {
        int p0 = (2 * q) * 512 + tid, p1 = (2 * q + 1) * 512 + tid;
        px2[q] = pack2(base[p0],         base[p1]);
        py2[q] = pack2(base[N + p0],     base[N + p1]);
        pz2[q] = pack2(base[2 * N + p0], base[2 * N + p1]);
    }
#pragma unroll
    for (int i = 0; i < 16; i++) dist[i] = 1e10f;

    __shared__ unsigned sM[2][32];
    __shared__ unsigned sI[2][32];
    if (tid == 0) {
        g_fps[b * S] = 0;
        __threadfence();
        g_prog[b] = 1;
    }
    if (tid >= 16 && tid < 32) {   // pad unused warp slots (16 warps only)
        sM[0][tid] = 0u;  sM[1][tid] = 0u;
        sI[0][tid] = 0xffffffffu; sI[1][tid] = 0xffffffffu;
    }
    int lane = tid & 31, wid = tid >> 5;
    float cx = base[0], cy = base[N], cz = base[2 * N];
    __syncthreads();

    for (int s = 1; s < S; s++) {
        unsigned long long ncx = pack2(-cx, -cx);
        unsigned long long ncy = pack2(-cy, -cy);
        unsigned long long ncz = pack2(-cz, -cz);
        // packed update: (p + (-c)) == (p - c); mul2/fma2/fma2 == scalar chain
#pragma unroll
        for (int q = 0; q < 8; q++) {
            unsigned long long dx = add2(px2[q], ncx);
            unsigned long long dy = add2(py2[q], ncy);
            unsigned long long dz = add2(pz2[q], ncz);
            unsigned long long d2 = mul2(dx, dx);
            fma2(d2, dy, dy);
            fma2(d2, dz, dz);
            float dlo, dhi; unpack2(d2, dlo, dhi);
            dist[2 * q]     = fminf(dist[2 * q],     dlo);
            dist[2 * q + 1] = fminf(dist[2 * q + 1], dhi);
        }
        // strict > keeps lowest j -> min point index for ties
        float bd = dist[0]; int bj = 0;
#pragma unroll
        for (int j = 1; j < 16; j++)
            if (dist[j] > bd) { bd = dist[j]; bj = j; }
        int bidx = (bj << 9) | tid;   // point index = j*512 + tid

        unsigned db = __float_as_uint(bd);   // d >= 0: bit order == float order
        unsigned mb = redux_max_u32(db);
        unsigned cand = (db == mb) ? (unsigned)bidx : 0xffffffffu;
        unsigned im = redux_min_u32(cand);
        int buf = s & 1;
        if (lane == 0) { sM[buf][wid] = mb; sI[buf][wid] = im; }
        __syncthreads();
        unsigned m2 = sM[buf][lane];
        unsigned i2 = sI[buf][lane];
        unsigned MB = redux_max_u32(m2);
        unsigned c2 = (m2 == MB) ? i2 : 0xffffffffu;
        unsigned I = redux_min_u32(c2);
        if (tid == 0) {
            g_fps[b * S + s] = (int)I;
            if ((s & 15) == 15) {      // batched publish (s=2047 -> prog=2048)
                __threadfence();
                g_prog[b] = s + 1;
            }
        }
        cx = __ldg(base + I); cy = __ldg(base + N + I); cz = __ldg(base + 2 * N + I);
    }
}

// =======================  worker (consumer) path  =======================
__device__ void worker_block(const float* __restrict__ coor, const float* __restrict__ fea,
                             const float* __restrict__ W, const float* __restrict__ bb,
                             const float* __restrict__ gamma, const float* __restrict__ beta,
                             const float* __restrict__ mean, const float* __restrict__ var,
                             float* __restrict__ out_coor, float* __restrict__ out_fea,
                             float* smem, int widx, int tid) {
    // ---- pre-phase: fold (worker 0) + feat build (all workers, 512 thr) ----
    if (widx == 0 && tid < 256) {
        int d = tid;
        float sc = gamma[d] * rsqrtf(var[d] + 1e-5f);
        for (int c = 0; c < 128; c++)
            g_Wt[c * D + d] = W[d * 131 + c] * sc;
        for (int c = 128; c < 131; c++)
            g_Wt[c * D + d] = W[d * 131 + c] * sc * 10.0f;
        g_Wt[131 * D + d] = 0.f;
        g_bias[d] = (bb[d] - mean[d]) * sc + beta[d];
    }
    for (int i = widx * 512 + tid; i < B * N * CP; i += NWORK * 512) {
        int c = i % CP;
        int bn = i / CP;
        int n = bn % N;
        int b = bn / N;
        float v;
        if (c < C)        v = fea[(b * C + c) * N + n];
        else if (c < 131) v = coor[(b * 3 + (c - C)) * N + n];
        else              v = 0.f;
        g_feat[i] = v;
    }
    __syncthreads();
    if (tid == 0) {
        __threadfence();
        atomicAdd((int*)&g_sync, 1);
        while (g_sync < NWORK) __nanosleep(128);
    }
    __syncthreads();
    __threadfence();
    if (tid >= 256) return;        // main loop uses 256 threads + named bars

    // ---- smem layout ----
    float* Wsh = smem;             // CP*D
    float* gsh = smem + CP * D;    // CP*K
    float* red = gsh + CP * K;     // 4*D
    __shared__ int   s_cnt;
    __shared__ float s_cd[CAP];
    __shared__ int   s_cidx[CAP];
    __shared__ int   s_sel[32];
    __shared__ int   s_nidx[32];
    __shared__ float s_cc[3];
    __shared__ int   s_ci;

    for (int i = tid; i < CP * D; i += 256) Wsh[i] = g_Wt[i];
    float biasv = g_bias[tid];

    unsigned sbase;
    asm("{ .reg .u64 t; cvta.to.shared.u64 t, %1; cvt.u32.u64 %0, t; }"
        : "=r"(sbase) : "l"(smem));
    int dt = tid & 63, kt = tid >> 6;
    unsigned waddr0 = sbase + (unsigned)(dt * 16);
    const float* gb = gsh + kt * 8;
    WBAR();

    for (int i = widx; i < B * S; i += NWORK) {
        int s = i >> 2, b = i & 3;          // (s,b) order tracks the fps frontier
        const float* base = coor + b * 3 * N;

        if (tid == 0) {
            while (g_prog[b] <= s) __nanosleep(64);
            __threadfence();
            s_ci = __ldcg(&g_fps[b * S + s]);
            s_cnt = 0;
        }
        WBAR();
        int ci = s_ci;
        float cx = __ldg(base + ci), cy = __ldg(base + N + ci), cz = __ldg(base + 2 * N + ci);
        if (tid < 3) {
            float v = (tid == 0) ? cx : (tid == 1) ? cy : cz;
            out_coor[(b * 3 + tid) * S + s] = v;
            s_cc[tid] = v;
        }
        float cc2 = cx * cx + cy * cy + cz * cz;

        // radius scan (expanded form matches reference)
        for (int p = tid; p < N; p += 256) {
            float x = base[p], y = base[N + p], z = base[2 * N + p];
            float pp = x * x + y * y + z * z;
            float dt2 = cx * x + cy * y + cz * z;
            float sq = cc2 + pp - 2.f * dt2;
            if (sq <= R2) {
                int pos = atomicAdd(&s_cnt, 1);
                if (pos < CAP) { s_cd[pos] = sq; s_cidx[pos] = p; }
            }
        }
        WBAR();
        int n = min(s_cnt, CAP);
        for (int c = tid; c < n; c += 256) {
            float dc = s_cd[c]; int ic = s_cidx[c];
            int r = 0;
            for (int j = 0; j < n; j++) {
                float dj = s_cd[j]; int ij = s_cidx[j];
                r += (dj < dc) || (dj == dc && ij < ic);
            }
            if (r < 32) s_sel[r] = ic;
        }
        WBAR();
        if (tid < 32) {
            int m = min(n, 32);
            s_nidx[tid] = (tid < m) ? s_sel[tid] : s_sel[0];
        }
        WBAR();

        // gather 32 neighbors x 132 channels (pure float4 copy)
        for (int q = tid; q < 32 * 33; q += 256) {
            int k = q & 31, cq = q >> 5;
            const float4 v = *(const float4*)(g_feat + (size_t)(b * N + s_nidx[k]) * CP + cq * 4);
            int c = cq * 4;
            gsh[(c + 0) * 32 + k] = v.x;
            gsh[(c + 1) * 32 + k] = v.y;
            gsh[(c + 2) * 32 + k] = v.z;
            gsh[(c + 3) * 32 + k] = v.w;
        }
        WBAR();

        unsigned long long acc[16];
#pragma unroll
        for (int q = 0; q < 16; q++) acc[q] = 0ull;
#pragma unroll 2
        for (int c = 0; c < CP; c++) {
            unsigned long long w0, w1;
            unsigned a0 = waddr0 + (unsigned)(c * (D * 4));
            asm volatile("ld.shared.v2.b64 {%0,%1}, [%2];" : "=l"(w0), "=l"(w1) : "r"(a0));
            float4 ga = *(const float4*)(gb + c * 32);
            float4 gc = *(const float4*)(gb + c * 32 + 4);
            unsigned long long g0 = pack2(ga.x, ga.x), g1 = pack2(ga.y, ga.y);
            unsigned long long g2 = pack2(ga.z, ga.z), g3 = pack2(ga.w, ga.w);
            unsigned long long g4 = pack2(gc.x, gc.x), g5 = pack2(gc.y, gc.y);
            unsigned long long g6 = pack2(gc.z, gc.z), g7 = pack2(gc.w, gc.w);
            fma2(acc[0],  g0, w0); fma2(acc[1],  g0, w1);
            fma2(acc[2],  g1, w0); fma2(acc[3],  g1, w1);
            fma2(acc[4],  g2, w0); fma2(acc[5],  g2, w1);
            fma2(acc[6],  g3, w0); fma2(acc[7],  g3, w1);
            fma2(acc[8],  g4, w0); fma2(acc[9],  g4, w1);
            fma2(acc[10], g5, w0); fma2(acc[11], g5, w1);
            fma2(acc[12], g6, w0); fma2(acc[13], g6, w1);
            fma2(acc[14], g7, w0); fma2(acc[15], g7, w1);
        }

        float mx[4];
#pragma unroll
        for (int l = 0; l < 4; l++) mx[l] = -1e30f;
#pragma unroll
        for (int ki = 0; ki < 8; ki++) {
            float a, bv;
            unpack2(acc[ki * 2 + 0], a, bv);
            mx[0] = fmaxf(mx[0], a); mx[1] = fmaxf(mx[1], bv);
            unpack2(acc[ki * 2 + 1], a, bv);
            mx[2] = fmaxf(mx[2], a); mx[3] = fmaxf(mx[3], bv);
        }
#pragma unroll
        for (int l = 0; l < 4; l++)
            red[kt * D + dt * 4 + l] = mx[l];
        WBAR();
        {
            float v = red[tid];
#pragma unroll
            for (int q = 1; q < 4; q++) v = fmaxf(v, red[q * D + tid]);
            float adj = Wsh[128 * D + tid] * s_cc[0]
                      + Wsh[129 * D + tid] * s_cc[1]
                      + Wsh[130 * D + tid] * s_cc[2];
            float o = v - adj + biasv;
            o = o > 0.f ? o : 0.f;
            out_fea[((size_t)b * D + tid) * S + s] = o;
        }
        WBAR();
    }
}

// =======================  fused persistent kernel  ======================
__global__ void __launch_bounds__(512, 1) fused_kernel(
    const float* __restrict__ coor, const float* __restrict__ fea,
    const float* __restrict__ W, const float* __restrict__ bb,
    const float* __restrict__ gamma, const float* __restrict__ beta,
    const float* __restrict__ mean, const float* __restrict__ var,
    float* __restrict__ out_coor, float* __restrict__ out_fea) {
    extern __shared__ float smem[];
    int cta = blockIdx.x, tid = threadIdx.x;
    if (cta < B) {
        fps_block(coor, cta, tid);
    } else {
        worker_block(coor, fea, W, bb, gamma, beta, mean, var,
                     out_coor, out_fea, smem, cta - B, tid);
    }
}

// ---------------- launch ----------------
extern "C" void kernel_launch(void* const* d_in, const int* in_sizes, int n_in,
                              void* d_out, int out_size) {
    const float* coor  = (const float*)d_in[0];
    const float* fea   = (const float*)d_in[1];
    const float* W     = (const float*)d_in[2];
    const float* bb    = (const float*)d_in[3];
    const float* gamma = (const float*)d_in[4];
    const float* beta  = (const float*)d_in[5];
    const float* mean  = (const float*)d_in[6];
    const float* var   = (const float*)d_in[7];

    float* out      = (float*)d_out;
    float* out_coor = out;              // (B,3,S)
    float* out_fea  = out + B * 3 * S;  // (B,2C,S)

    init_kernel<<<1, 32>>>();

    const int smem_bytes = (CP * D + CP * K + 4 * D) * 4;  // 156160 B
    cudaFuncSetAttribute(fused_kernel, cudaFuncAttributeMaxDynamicSharedMemorySize, smem_bytes);
    fused_kernel<<<NCTA, 512, smem_bytes>>>(coor, fea, W, bb, gamma, beta,
                                            mean, var, out_coor, out_fea);
}